// round 3
// baseline (speedup 1.0000x reference)
#include <cuda_runtime.h>

namespace {

constexpr int Cc = 192;
constexpr int Hh = 128;
constexpr int Ww = 128;
constexpr int ROWS_PER_WARP = 16;
constexpr int WARPS = 4;
constexpr int THREADS = WARPS * 32;
constexpr int ROWS_PER_BLOCK = WARPS * ROWS_PER_WARP;   // 64
constexpr int STRIPS_PER_PLANE = Hh / ROWS_PER_BLOCK;   // 2

__device__ __forceinline__ float ex2_approx(float t) {
    float r;
    asm("ex2.approx.f32 %0, %1;" : "=f"(r) : "f"(t));
    return r;
}
__device__ __forceinline__ float rcp_approx(float t) {
    float r;
    asm("rcp.approx.f32 %0, %1;" : "=f"(r) : "f"(t));
    return r;
}

// sigmoid(x*gw+gb) with gw,gb pre-scaled by -log2(e):
// s = 1 / (1 + 2^(x*a + b))
__device__ __forceinline__ float gate_sig(float v, float a, float b) {
    return rcp_approx(1.0f + ex2_approx(fmaf(v, a, b)));
}

// acc = max(acc, patch + t*k) over one input row (halo L/R), one kernel row
__device__ __forceinline__ void relax(float4& acc, const float4& t,
                                      float L, const float4& v, float R,
                                      float kl, float kc, float kr) {
    acc.x = fmaxf(acc.x, fmaf(t.x, kl, L));
    acc.x = fmaxf(acc.x, fmaf(t.x, kc, v.x));
    acc.x = fmaxf(acc.x, fmaf(t.x, kr, v.y));

    acc.y = fmaxf(acc.y, fmaf(t.y, kl, v.x));
    acc.y = fmaxf(acc.y, fmaf(t.y, kc, v.y));
    acc.y = fmaxf(acc.y, fmaf(t.y, kr, v.z));

    acc.z = fmaxf(acc.z, fmaf(t.z, kl, v.y));
    acc.z = fmaxf(acc.z, fmaf(t.z, kc, v.z));
    acc.z = fmaxf(acc.z, fmaf(t.z, kr, v.w));

    acc.w = fmaxf(acc.w, fmaf(t.w, kl, v.z));
    acc.w = fmaxf(acc.w, fmaf(t.w, kc, v.w));
    acc.w = fmaxf(acc.w, fmaf(t.w, kr, R));
}

// same but initializes acc (saves 4 FMNMX)
__device__ __forceinline__ void relax_init(float4& acc, const float4& t,
                                           float L, const float4& v, float R,
                                           float kl, float kc, float kr) {
    acc.x = fmaf(t.x, kc, v.x);
    acc.y = fmaf(t.y, kc, v.y);
    acc.z = fmaf(t.z, kc, v.z);
    acc.w = fmaf(t.w, kc, v.w);

    acc.x = fmaxf(acc.x, fmaf(t.x, kl, L));
    acc.x = fmaxf(acc.x, fmaf(t.x, kr, v.y));

    acc.y = fmaxf(acc.y, fmaf(t.y, kl, v.x));
    acc.y = fmaxf(acc.y, fmaf(t.y, kr, v.z));

    acc.z = fmaxf(acc.z, fmaf(t.z, kl, v.y));
    acc.z = fmaxf(acc.z, fmaf(t.z, kr, v.w));

    acc.w = fmaxf(acc.w, fmaf(t.w, kl, v.z));
    acc.w = fmaxf(acc.w, fmaf(t.w, kr, R));
}

__global__ void __launch_bounds__(THREADS, 11)
dynmorph_kernel(const float* __restrict__ x,
                const float* __restrict__ kern,
                const float* __restrict__ gw,
                const float* __restrict__ gb,
                float* __restrict__ out) {
    const int strip = blockIdx.x;
    const int plane = strip / STRIPS_PER_PLANE;
    const int half  = strip % STRIPS_PER_PLANE;
    const int c     = plane % Cc;
    const int warp  = threadIdx.x >> 5;
    const int lane  = threadIdx.x & 31;

    const float* __restrict__ xp = x   + (size_t)plane * (Hh * Ww);
    float*       __restrict__ op = out + (size_t)plane * (Hh * Ww);

    const float k0 = __ldg(&kern[c * 9 + 0]);
    const float k1 = __ldg(&kern[c * 9 + 1]);
    const float k2 = __ldg(&kern[c * 9 + 2]);
    const float k3 = __ldg(&kern[c * 9 + 3]);
    const float k4 = __ldg(&kern[c * 9 + 4]);
    const float k5 = __ldg(&kern[c * 9 + 5]);
    const float k6 = __ldg(&kern[c * 9 + 6]);
    const float k7 = __ldg(&kern[c * 9 + 7]);
    const float k8 = __ldg(&kern[c * 9 + 8]);
    // fold -log2(e) into the gate so sigmoid = rcp(1 + ex2(x*a + b))
    const float ga = __ldg(&gw[c]) * -1.4426950408889634f;
    const float gbp = __ldg(&gb[c]) * -1.4426950408889634f;

    const int h0  = half * ROWS_PER_BLOCK + warp * ROWS_PER_WARP;
    const int col = lane * 4;

    // rolling 3-row register window + 1 prefetch buffer
    float4 rm, r0, rp, rnext;
    float Lm, Rm, L0, R0, Lp, Rp;

    // row h0-1 (zero pad at top of plane)
    if (h0 == 0) {
        rm = make_float4(0.f, 0.f, 0.f, 0.f);
    } else {
        rm = *reinterpret_cast<const float4*>(xp + (size_t)(h0 - 1) * Ww + col);
    }
    {
        float l = __shfl_up_sync(0xffffffffu, rm.w, 1);
        float r = __shfl_down_sync(0xffffffffu, rm.x, 1);
        Lm = (lane == 0) ? 0.f : l;
        Rm = (lane == 31) ? 0.f : r;
    }

    // row h0
    r0 = *reinterpret_cast<const float4*>(xp + (size_t)h0 * Ww + col);
    {
        float l = __shfl_up_sync(0xffffffffu, r0.w, 1);
        float r = __shfl_down_sync(0xffffffffu, r0.x, 1);
        L0 = (lane == 0) ? 0.f : l;
        R0 = (lane == 31) ? 0.f : r;
    }

    // row h0+1 in flight (always valid: h0+1 <= 127 inside a strip start)
    rp = *reinterpret_cast<const float4*>(xp + (size_t)(h0 + 1) * Ww + col);

#pragma unroll 4
    for (int rr = 0; rr < ROWS_PER_WARP; rr++) {
        const int h = h0 + rr;

        // prefetch row h+2 (in flight during this row's compute)
        if (h + 2 < Hh) {
            rnext = *reinterpret_cast<const float4*>(xp + (size_t)(h + 2) * Ww + col);
        } else {
            rnext = make_float4(0.f, 0.f, 0.f, 0.f);
        }

        // halos for rp (row h+1)
        {
            float l = __shfl_up_sync(0xffffffffu, rp.w, 1);
            float r = __shfl_down_sync(0xffffffffu, rp.x, 1);
            Lp = (lane == 0) ? 0.f : l;
            Rp = (lane == 31) ? 0.f : r;
        }

        // gate from center row
        float4 t;
        t.x = gate_sig(r0.x, ga, gbp);
        t.y = gate_sig(r0.y, ga, gbp);
        t.z = gate_sig(r0.z, ga, gbp);
        t.w = gate_sig(r0.w, ga, gbp);

        float4 acc;
        relax_init(acc, t, Lm, rm, Rm, k0, k1, k2);  // row h-1
        relax(acc, t, L0, r0, R0, k3, k4, k5);       // row h
        relax(acc, t, Lp, rp, Rp, k6, k7, k8);       // row h+1

        *reinterpret_cast<float4*>(op + (size_t)h * Ww + col) = acc;

        // roll window down
        rm = r0; Lm = L0; Rm = R0;
        r0 = rp; L0 = Lp; R0 = Rp;
        rp = rnext;
    }
}

}  // namespace

extern "C" void kernel_launch(void* const* d_in, const int* in_sizes, int n_in,
                              void* d_out, int out_size) {
    const float* x    = (const float*)d_in[0];
    const float* kern = (const float*)d_in[1];
    const float* gw   = (const float*)d_in[2];
    const float* gb   = (const float*)d_in[3];
    float* out        = (float*)d_out;

    const int planes = in_sizes[0] / (Hh * Ww);  // B * C = 1536
    dynmorph_kernel<<<planes * STRIPS_PER_PLANE, THREADS>>>(x, kern, gw, gb, out);
}

// round 4
// speedup vs baseline: 1.0386x; 1.0386x over previous
#include <cuda_runtime.h>

namespace {

constexpr int Cc = 192;
constexpr int Hh = 128;
constexpr int Ww = 128;
constexpr int ROWS_PER_WARP = 16;
constexpr int WARPS = 4;
constexpr int THREADS = WARPS * 32;
constexpr int ROWS_PER_BLOCK = WARPS * ROWS_PER_WARP;   // 64
constexpr int STRIPS_PER_PLANE = Hh / ROWS_PER_BLOCK;   // 2

using u64 = unsigned long long;

__device__ __forceinline__ u64 pk(float lo, float hi) {
    u64 r; asm("mov.b64 %0, {%1, %2};" : "=l"(r) : "f"(lo), "f"(hi)); return r;
}
__device__ __forceinline__ float2 upk(u64 v) {
    float2 f; asm("mov.b64 {%0, %1}, %2;" : "=f"(f.x), "=f"(f.y) : "l"(v)); return f;
}
// packed dual FMA (FFMA2) — PTX-only on sm_103a
__device__ __forceinline__ u64 fma2(u64 a, u64 b, u64 c) {
    u64 d; asm("fma.rn.f32x2 %0, %1, %2, %3;" : "=l"(d) : "l"(a), "l"(b), "l"(c));
    return d;
}

__device__ __forceinline__ float ex2_approx(float t) {
    float r; asm("ex2.approx.f32 %0, %1;" : "=f"(r) : "f"(t)); return r;
}
__device__ __forceinline__ float rcp_approx(float t) {
    float r; asm("rcp.approx.f32 %0, %1;" : "=f"(r) : "f"(t)); return r;
}
// sigmoid(x*gw+gb) with gw,gb pre-scaled by -log2(e): 1/(1+2^(x*a+b))
__device__ __forceinline__ float gate_sig(float v, float a, float b) {
    return rcp_approx(1.0f + ex2_approx(fmaf(v, a, b)));
}

// one kernel-row relaxation over 4 pixels via packed FFMA2
template <bool INIT>
__device__ __forceinline__ void relax2(float4& acc, u64 t01, u64 t23,
                                       float L, const float4& v, float R,
                                       u64 kl2, u64 kc2, u64 kr2) {
    const u64 pLx = pk(L,   v.x);
    const u64 pxy = pk(v.x, v.y);
    const u64 pyz = pk(v.y, v.z);
    const u64 pzw = pk(v.z, v.w);
    const u64 pwR = pk(v.w, R);

    float2 s;
    s = upk(fma2(t01, kc2, pxy));
    if (INIT) { acc.x = s.x; acc.y = s.y; }
    else      { acc.x = fmaxf(acc.x, s.x); acc.y = fmaxf(acc.y, s.y); }
    s = upk(fma2(t23, kc2, pzw));
    if (INIT) { acc.z = s.x; acc.w = s.y; }
    else      { acc.z = fmaxf(acc.z, s.x); acc.w = fmaxf(acc.w, s.y); }

    s = upk(fma2(t01, kl2, pLx));
    acc.x = fmaxf(acc.x, s.x); acc.y = fmaxf(acc.y, s.y);
    s = upk(fma2(t01, kr2, pyz));
    acc.x = fmaxf(acc.x, s.x); acc.y = fmaxf(acc.y, s.y);
    s = upk(fma2(t23, kl2, pyz));
    acc.z = fmaxf(acc.z, s.x); acc.w = fmaxf(acc.w, s.y);
    s = upk(fma2(t23, kr2, pwR));
    acc.z = fmaxf(acc.z, s.x); acc.w = fmaxf(acc.w, s.y);
}

__global__ void __launch_bounds__(THREADS, 11)
dynmorph_kernel(const float* __restrict__ x,
                const float* __restrict__ kern,
                const float* __restrict__ gw,
                const float* __restrict__ gb,
                float* __restrict__ out) {
    const int strip = blockIdx.x;
    const int plane = strip / STRIPS_PER_PLANE;
    const int half  = strip % STRIPS_PER_PLANE;
    const int c     = plane % Cc;
    const int warp  = threadIdx.x >> 5;
    const int lane  = threadIdx.x & 31;

    const float* __restrict__ xp = x   + (size_t)plane * (Hh * Ww);
    float*       __restrict__ op = out + (size_t)plane * (Hh * Ww);

    // broadcast kernel taps as f32x2 pairs (hoisted)
    const u64 k0_2 = pk(__ldg(&kern[c*9+0]), __ldg(&kern[c*9+0]));
    const u64 k1_2 = pk(__ldg(&kern[c*9+1]), __ldg(&kern[c*9+1]));
    const u64 k2_2 = pk(__ldg(&kern[c*9+2]), __ldg(&kern[c*9+2]));
    const u64 k3_2 = pk(__ldg(&kern[c*9+3]), __ldg(&kern[c*9+3]));
    const u64 k4_2 = pk(__ldg(&kern[c*9+4]), __ldg(&kern[c*9+4]));
    const u64 k5_2 = pk(__ldg(&kern[c*9+5]), __ldg(&kern[c*9+5]));
    const u64 k6_2 = pk(__ldg(&kern[c*9+6]), __ldg(&kern[c*9+6]));
    const u64 k7_2 = pk(__ldg(&kern[c*9+7]), __ldg(&kern[c*9+7]));
    const u64 k8_2 = pk(__ldg(&kern[c*9+8]), __ldg(&kern[c*9+8]));
    // fold -log2(e) so sigmoid = rcp(1 + ex2(x*a + b))
    const float ga  = __ldg(&gw[c]) * -1.4426950408889634f;
    const float gbp = __ldg(&gb[c]) * -1.4426950408889634f;

    const int h0  = half * ROWS_PER_BLOCK + warp * ROWS_PER_WARP;
    const int col = lane * 4;

    float4 rm, r0, rp;
    float Lm, Rm, L0, R0, Lp, Rp;

    // row h0-1 (zero pad at top of plane; uniform per warp)
    if (h0 == 0) {
        rm = make_float4(0.f, 0.f, 0.f, 0.f);
    } else {
        rm = *reinterpret_cast<const float4*>(xp + (size_t)(h0 - 1) * Ww + col);
    }
    {
        float l = __shfl_up_sync(0xffffffffu, rm.w, 1);
        float r = __shfl_down_sync(0xffffffffu, rm.x, 1);
        Lm = (lane == 0) ? 0.f : l;
        Rm = (lane == 31) ? 0.f : r;
    }

    // row h0
    r0 = *reinterpret_cast<const float4*>(xp + (size_t)h0 * Ww + col);
    {
        float l = __shfl_up_sync(0xffffffffu, r0.w, 1);
        float r = __shfl_down_sync(0xffffffffu, r0.x, 1);
        L0 = (lane == 0) ? 0.f : l;
        R0 = (lane == 31) ? 0.f : r;
    }

    // rr = 0..14: row h+1 = h0+rr+1 <= h0+15 <= 127 always in-bounds -> branch-free
#pragma unroll 5
    for (int rr = 0; rr < ROWS_PER_WARP - 1; rr++) {
        const int h = h0 + rr;

        rp = *reinterpret_cast<const float4*>(xp + (size_t)(h + 1) * Ww + col);
        {
            float l = __shfl_up_sync(0xffffffffu, rp.w, 1);
            float r = __shfl_down_sync(0xffffffffu, rp.x, 1);
            Lp = (lane == 0) ? 0.f : l;
            Rp = (lane == 31) ? 0.f : r;
        }

        const u64 t01 = pk(gate_sig(r0.x, ga, gbp), gate_sig(r0.y, ga, gbp));
        const u64 t23 = pk(gate_sig(r0.z, ga, gbp), gate_sig(r0.w, ga, gbp));

        float4 acc;
        relax2<true >(acc, t01, t23, Lm, rm, Rm, k0_2, k1_2, k2_2);
        relax2<false>(acc, t01, t23, L0, r0, R0, k3_2, k4_2, k5_2);
        relax2<false>(acc, t01, t23, Lp, rp, Rp, k6_2, k7_2, k8_2);

        *reinterpret_cast<float4*>(op + (size_t)h * Ww + col) = acc;

        rm = r0; Lm = L0; Rm = R0;
        r0 = rp; L0 = Lp; R0 = Rp;
    }

    // epilogue rr = 15: row h+1 may be the bottom pad (uniform per warp)
    {
        const int h = h0 + ROWS_PER_WARP - 1;
        if (h + 1 < Hh) {
            rp = *reinterpret_cast<const float4*>(xp + (size_t)(h + 1) * Ww + col);
        } else {
            rp = make_float4(0.f, 0.f, 0.f, 0.f);
        }
        {
            float l = __shfl_up_sync(0xffffffffu, rp.w, 1);
            float r = __shfl_down_sync(0xffffffffu, rp.x, 1);
            Lp = (lane == 0) ? 0.f : l;
            Rp = (lane == 31) ? 0.f : r;
        }

        const u64 t01 = pk(gate_sig(r0.x, ga, gbp), gate_sig(r0.y, ga, gbp));
        const u64 t23 = pk(gate_sig(r0.z, ga, gbp), gate_sig(r0.w, ga, gbp));

        float4 acc;
        relax2<true >(acc, t01, t23, Lm, rm, Rm, k0_2, k1_2, k2_2);
        relax2<false>(acc, t01, t23, L0, r0, R0, k3_2, k4_2, k5_2);
        relax2<false>(acc, t01, t23, Lp, rp, Rp, k6_2, k7_2, k8_2);

        *reinterpret_cast<float4*>(op + (size_t)h * Ww + col) = acc;
    }
}

}  // namespace

extern "C" void kernel_launch(void* const* d_in, const int* in_sizes, int n_in,
                              void* d_out, int out_size) {
    const float* x    = (const float*)d_in[0];
    const float* kern = (const float*)d_in[1];
    const float* gw   = (const float*)d_in[2];
    const float* gb   = (const float*)d_in[3];
    float* out        = (float*)d_out;

    const int planes = in_sizes[0] / (Hh * Ww);  // B * C = 1536
    dynmorph_kernel<<<planes * STRIPS_PER_PLANE, THREADS>>>(x, kern, gw, gb, out);
}

// round 6
// speedup vs baseline: 1.1446x; 1.1020x over previous
#include <cuda_runtime.h>

namespace {

constexpr int Cc = 192;
constexpr int Hh = 128;
constexpr int Ww = 128;
constexpr int ROWS_PER_WARP = 16;
constexpr int WARPS = 4;
constexpr int THREADS = WARPS * 32;
constexpr int ROWS_PER_BLOCK = WARPS * ROWS_PER_WARP;   // 64
constexpr int STRIPS_PER_PLANE = Hh / ROWS_PER_BLOCK;   // 2

__device__ __forceinline__ float tanh_approx(float t) {
    float r; asm("tanh.approx.f32 %0, %1;" : "=f"(r) : "f"(t)); return r;
}
// sigmoid(x*gw+gb) = 0.5*tanh((x*gw+gb)/2) + 0.5, with gw/2, gb/2 prefolded
__device__ __forceinline__ float gate_sig(float v, float a, float b) {
    return fmaf(tanh_approx(fmaf(v, a, b)), 0.5f, 0.5f);
}

// acc = max(acc, patch + t*k) over one input row (halo L/R), one kernel row
__device__ __forceinline__ void relax(float4& acc, const float4& t,
                                      float L, const float4& v, float R,
                                      float kl, float kc, float kr) {
    acc.x = fmaxf(acc.x, fmaf(t.x, kl, L));
    acc.x = fmaxf(acc.x, fmaf(t.x, kc, v.x));
    acc.x = fmaxf(acc.x, fmaf(t.x, kr, v.y));

    acc.y = fmaxf(acc.y, fmaf(t.y, kl, v.x));
    acc.y = fmaxf(acc.y, fmaf(t.y, kc, v.y));
    acc.y = fmaxf(acc.y, fmaf(t.y, kr, v.z));

    acc.z = fmaxf(acc.z, fmaf(t.z, kl, v.y));
    acc.z = fmaxf(acc.z, fmaf(t.z, kc, v.z));
    acc.z = fmaxf(acc.z, fmaf(t.z, kr, v.w));

    acc.w = fmaxf(acc.w, fmaf(t.w, kl, v.z));
    acc.w = fmaxf(acc.w, fmaf(t.w, kc, v.w));
    acc.w = fmaxf(acc.w, fmaf(t.w, kr, R));
}

// same but initializes acc (saves 4 FMNMX)
__device__ __forceinline__ void relax_init(float4& acc, const float4& t,
                                           float L, const float4& v, float R,
                                           float kl, float kc, float kr) {
    acc.x = fmaf(t.x, kc, v.x);
    acc.y = fmaf(t.y, kc, v.y);
    acc.z = fmaf(t.z, kc, v.z);
    acc.w = fmaf(t.w, kc, v.w);

    acc.x = fmaxf(acc.x, fmaf(t.x, kl, L));
    acc.x = fmaxf(acc.x, fmaf(t.x, kr, v.y));

    acc.y = fmaxf(acc.y, fmaf(t.y, kl, v.x));
    acc.y = fmaxf(acc.y, fmaf(t.y, kr, v.z));

    acc.z = fmaxf(acc.z, fmaf(t.z, kl, v.y));
    acc.z = fmaxf(acc.z, fmaf(t.z, kr, v.w));

    acc.w = fmaxf(acc.w, fmaf(t.w, kl, v.z));
    acc.w = fmaxf(acc.w, fmaf(t.w, kr, R));
}

__global__ void __launch_bounds__(THREADS, 12)
dynmorph_kernel(const float* __restrict__ x,
                const float* __restrict__ kern,
                const float* __restrict__ gw,
                const float* __restrict__ gb,
                float* __restrict__ out) {
    const int strip = blockIdx.x;
    const int plane = strip / STRIPS_PER_PLANE;
    const int half  = strip % STRIPS_PER_PLANE;
    const int c     = plane % Cc;
    const int warp  = threadIdx.x >> 5;
    const int lane  = threadIdx.x & 31;

    const float* __restrict__ xp = x   + (size_t)plane * (Hh * Ww);
    float*       __restrict__ op = out + (size_t)plane * (Hh * Ww);

    const float k0 = __ldg(&kern[c * 9 + 0]);
    const float k1 = __ldg(&kern[c * 9 + 1]);
    const float k2 = __ldg(&kern[c * 9 + 2]);
    const float k3 = __ldg(&kern[c * 9 + 3]);
    const float k4 = __ldg(&kern[c * 9 + 4]);
    const float k5 = __ldg(&kern[c * 9 + 5]);
    const float k6 = __ldg(&kern[c * 9 + 6]);
    const float k7 = __ldg(&kern[c * 9 + 7]);
    const float k8 = __ldg(&kern[c * 9 + 8]);
    // fold the /2 of the tanh-sigmoid identity into the gate params
    const float ga  = __ldg(&gw[c]) * 0.5f;
    const float gbp = __ldg(&gb[c]) * 0.5f;

    const int h0  = half * ROWS_PER_BLOCK + warp * ROWS_PER_WARP;
    const int col = lane * 4;

    const float* rowptr = xp + (size_t)h0 * Ww + col;
    float*       outptr = op + (size_t)h0 * Ww + col;

    float4 rm, r0, rp;
    float Lm, Rm, L0, R0, Lp, Rp;

    // row h0-1 (zero pad at top of plane; uniform branch per warp)
    if (h0 == 0) {
        rm = make_float4(0.f, 0.f, 0.f, 0.f);
    } else {
        rm = *reinterpret_cast<const float4*>(rowptr - Ww);
    }
    {
        float l = __shfl_up_sync(0xffffffffu, rm.w, 1);
        float r = __shfl_down_sync(0xffffffffu, rm.x, 1);
        Lm = (lane == 0) ? 0.f : l;
        Rm = (lane == 31) ? 0.f : r;
    }

    // row h0
    r0 = *reinterpret_cast<const float4*>(rowptr);
    {
        float l = __shfl_up_sync(0xffffffffu, r0.w, 1);
        float r = __shfl_down_sync(0xffffffffu, r0.x, 1);
        L0 = (lane == 0) ? 0.f : l;
        R0 = (lane == 31) ? 0.f : r;
    }

    // rr = 0..14: row h+1 = h0+rr+1 <= 127 always in-bounds -> branch-free.
    // unroll 3 matches the 3-buffer rotation so rolling copies rename away.
#pragma unroll 3
    for (int rr = 0; rr < ROWS_PER_WARP - 1; rr++) {
        rp = *reinterpret_cast<const float4*>(rowptr + (size_t)(rr + 1) * Ww);
        {
            float l = __shfl_up_sync(0xffffffffu, rp.w, 1);
            float r = __shfl_down_sync(0xffffffffu, rp.x, 1);
            Lp = (lane == 0) ? 0.f : l;
            Rp = (lane == 31) ? 0.f : r;
        }

        float4 t;
        t.x = gate_sig(r0.x, ga, gbp);
        t.y = gate_sig(r0.y, ga, gbp);
        t.z = gate_sig(r0.z, ga, gbp);
        t.w = gate_sig(r0.w, ga, gbp);

        float4 acc;
        relax_init(acc, t, Lm, rm, Rm, k0, k1, k2);  // row h-1
        relax(acc, t, L0, r0, R0, k3, k4, k5);       // row h
        relax(acc, t, Lp, rp, Rp, k6, k7, k8);       // row h+1

        *reinterpret_cast<float4*>(outptr + (size_t)rr * Ww) = acc;

        rm = r0; Lm = L0; Rm = R0;
        r0 = rp; L0 = Lp; R0 = Rp;
    }

    // epilogue rr = 15: row h+1 may be the bottom pad (uniform per warp)
    {
        const int h = h0 + ROWS_PER_WARP - 1;
        if (h + 1 < Hh) {
            rp = *reinterpret_cast<const float4*>(rowptr + (size_t)ROWS_PER_WARP * Ww);
        } else {
            rp = make_float4(0.f, 0.f, 0.f, 0.f);
        }
        {
            float l = __shfl_up_sync(0xffffffffu, rp.w, 1);
            float r = __shfl_down_sync(0xffffffffu, rp.x, 1);
            Lp = (lane == 0) ? 0.f : l;
            Rp = (lane == 31) ? 0.f : r;
        }

        float4 t;
        t.x = gate_sig(r0.x, ga, gbp);
        t.y = gate_sig(r0.y, ga, gbp);
        t.z = gate_sig(r0.z, ga, gbp);
        t.w = gate_sig(r0.w, ga, gbp);

        float4 acc;
        relax_init(acc, t, Lm, rm, Rm, k0, k1, k2);
        relax(acc, t, L0, r0, R0, k3, k4, k5);
        relax(acc, t, Lp, rp, Rp, k6, k7, k8);

        *reinterpret_cast<float4*>(outptr + (size_t)(ROWS_PER_WARP - 1) * Ww) = acc;
    }
}

}  // namespace

extern "C" void kernel_launch(void* const* d_in, const int* in_sizes, int n_in,
                              void* d_out, int out_size) {
    const float* x    = (const float*)d_in[0];
    const float* kern = (const float*)d_in[1];
    const float* gw   = (const float*)d_in[2];
    const float* gb   = (const float*)d_in[3];
    float* out        = (float*)d_out;

    const int planes = in_sizes[0] / (Hh * Ww);  // B * C = 1536
    dynmorph_kernel<<<planes * STRIPS_PER_PLANE, THREADS>>>(x, kern, gw, gb, out);
}

// round 7
// speedup vs baseline: 1.1786x; 1.0298x over previous
#include <cuda_runtime.h>

namespace {

constexpr int Cc = 192;
constexpr int Hh = 128;
constexpr int Ww = 128;
constexpr int ROWS_PER_WARP = 8;
constexpr int WARPS = 4;
constexpr int THREADS = WARPS * 32;
constexpr int ROWS_PER_BLOCK = WARPS * ROWS_PER_WARP;   // 32
constexpr int STRIPS_PER_PLANE = Hh / ROWS_PER_BLOCK;   // 4

__device__ __forceinline__ float tanh_approx(float t) {
    float r; asm("tanh.approx.f32 %0, %1;" : "=f"(r) : "f"(t)); return r;
}
// sigmoid(x*gw+gb) = 0.5*tanh((x*gw+gb)/2) + 0.5, with gw/2, gb/2 prefolded
__device__ __forceinline__ float gate_sig(float v, float a, float b) {
    return fmaf(tanh_approx(fmaf(v, a, b)), 0.5f, 0.5f);
}

// acc = max(acc, patch + t*k) over one input row (halo L/R), one kernel row
__device__ __forceinline__ void relax(float4& acc, const float4& t,
                                      float L, const float4& v, float R,
                                      float kl, float kc, float kr) {
    acc.x = fmaxf(acc.x, fmaf(t.x, kl, L));
    acc.x = fmaxf(acc.x, fmaf(t.x, kc, v.x));
    acc.x = fmaxf(acc.x, fmaf(t.x, kr, v.y));

    acc.y = fmaxf(acc.y, fmaf(t.y, kl, v.x));
    acc.y = fmaxf(acc.y, fmaf(t.y, kc, v.y));
    acc.y = fmaxf(acc.y, fmaf(t.y, kr, v.z));

    acc.z = fmaxf(acc.z, fmaf(t.z, kl, v.y));
    acc.z = fmaxf(acc.z, fmaf(t.z, kc, v.z));
    acc.z = fmaxf(acc.z, fmaf(t.z, kr, v.w));

    acc.w = fmaxf(acc.w, fmaf(t.w, kl, v.z));
    acc.w = fmaxf(acc.w, fmaf(t.w, kc, v.w));
    acc.w = fmaxf(acc.w, fmaf(t.w, kr, R));
}

// same but initializes acc (saves 4 FMNMX)
__device__ __forceinline__ void relax_init(float4& acc, const float4& t,
                                           float L, const float4& v, float R,
                                           float kl, float kc, float kr) {
    acc.x = fmaf(t.x, kc, v.x);
    acc.y = fmaf(t.y, kc, v.y);
    acc.z = fmaf(t.z, kc, v.z);
    acc.w = fmaf(t.w, kc, v.w);

    acc.x = fmaxf(acc.x, fmaf(t.x, kl, L));
    acc.x = fmaxf(acc.x, fmaf(t.x, kr, v.y));

    acc.y = fmaxf(acc.y, fmaf(t.y, kl, v.x));
    acc.y = fmaxf(acc.y, fmaf(t.y, kr, v.z));

    acc.z = fmaxf(acc.z, fmaf(t.z, kl, v.y));
    acc.z = fmaxf(acc.z, fmaf(t.z, kr, v.w));

    acc.w = fmaxf(acc.w, fmaf(t.w, kl, v.z));
    acc.w = fmaxf(acc.w, fmaf(t.w, kr, R));
}

__global__ void __launch_bounds__(THREADS, 12)
dynmorph_kernel(const float* __restrict__ x,
                const float* __restrict__ kern,
                const float* __restrict__ gw,
                const float* __restrict__ gb,
                float* __restrict__ out) {
    const int strip = blockIdx.x;
    const int plane = strip / STRIPS_PER_PLANE;
    const int part  = strip % STRIPS_PER_PLANE;
    const int c     = plane % Cc;
    const int warp  = threadIdx.x >> 5;
    const int lane  = threadIdx.x & 31;

    const float* __restrict__ xp = x   + (size_t)plane * (Hh * Ww);
    float*       __restrict__ op = out + (size_t)plane * (Hh * Ww);

    const float k0 = __ldg(&kern[c * 9 + 0]);
    const float k1 = __ldg(&kern[c * 9 + 1]);
    const float k2 = __ldg(&kern[c * 9 + 2]);
    const float k3 = __ldg(&kern[c * 9 + 3]);
    const float k4 = __ldg(&kern[c * 9 + 4]);
    const float k5 = __ldg(&kern[c * 9 + 5]);
    const float k6 = __ldg(&kern[c * 9 + 6]);
    const float k7 = __ldg(&kern[c * 9 + 7]);
    const float k8 = __ldg(&kern[c * 9 + 8]);
    // fold the /2 of the tanh-sigmoid identity into the gate params
    const float ga  = __ldg(&gw[c]) * 0.5f;
    const float gbp = __ldg(&gb[c]) * 0.5f;

    const int h0  = part * ROWS_PER_BLOCK + warp * ROWS_PER_WARP;
    const int col = lane * 4;

    const float* rowptr = xp + (size_t)h0 * Ww + col;
    float*       outptr = op + (size_t)h0 * Ww + col;

    float4 rm, r0, rp;
    float Lm, Rm, L0, R0, Lp, Rp;

    // row h0-1 (zero pad at top of plane; uniform branch per warp)
    if (h0 == 0) {
        rm = make_float4(0.f, 0.f, 0.f, 0.f);
    } else {
        rm = *reinterpret_cast<const float4*>(rowptr - Ww);
    }
    {
        float l = __shfl_up_sync(0xffffffffu, rm.w, 1);
        float r = __shfl_down_sync(0xffffffffu, rm.x, 1);
        Lm = (lane == 0) ? 0.f : l;
        Rm = (lane == 31) ? 0.f : r;
    }

    // row h0
    r0 = *reinterpret_cast<const float4*>(rowptr);
    {
        float l = __shfl_up_sync(0xffffffffu, r0.w, 1);
        float r = __shfl_down_sync(0xffffffffu, r0.x, 1);
        L0 = (lane == 0) ? 0.f : l;
        R0 = (lane == 31) ? 0.f : r;
    }

    // rr = 0..6: row h+1 = h0+rr+1 <= 127 always in-bounds -> branch-free.
#pragma unroll 7
    for (int rr = 0; rr < ROWS_PER_WARP - 1; rr++) {
        rp = *reinterpret_cast<const float4*>(rowptr + (size_t)(rr + 1) * Ww);
        {
            float l = __shfl_up_sync(0xffffffffu, rp.w, 1);
            float r = __shfl_down_sync(0xffffffffu, rp.x, 1);
            Lp = (lane == 0) ? 0.f : l;
            Rp = (lane == 31) ? 0.f : r;
        }

        float4 t;
        t.x = gate_sig(r0.x, ga, gbp);
        t.y = gate_sig(r0.y, ga, gbp);
        t.z = gate_sig(r0.z, ga, gbp);
        t.w = gate_sig(r0.w, ga, gbp);

        float4 acc;
        relax_init(acc, t, Lm, rm, Rm, k0, k1, k2);  // row h-1
        relax(acc, t, L0, r0, R0, k3, k4, k5);       // row h
        relax(acc, t, Lp, rp, Rp, k6, k7, k8);       // row h+1

        *reinterpret_cast<float4*>(outptr + (size_t)rr * Ww) = acc;

        rm = r0; Lm = L0; Rm = R0;
        r0 = rp; L0 = Lp; R0 = Rp;
    }

    // epilogue: last row of the strip; row h+1 may be the bottom pad
    {
        const int h = h0 + ROWS_PER_WARP - 1;
        if (h + 1 < Hh) {
            rp = *reinterpret_cast<const float4*>(rowptr + (size_t)ROWS_PER_WARP * Ww);
        } else {
            rp = make_float4(0.f, 0.f, 0.f, 0.f);
        }
        {
            float l = __shfl_up_sync(0xffffffffu, rp.w, 1);
            float r = __shfl_down_sync(0xffffffffu, rp.x, 1);
            Lp = (lane == 0) ? 0.f : l;
            Rp = (lane == 31) ? 0.f : r;
        }

        float4 t;
        t.x = gate_sig(r0.x, ga, gbp);
        t.y = gate_sig(r0.y, ga, gbp);
        t.z = gate_sig(r0.z, ga, gbp);
        t.w = gate_sig(r0.w, ga, gbp);

        float4 acc;
        relax_init(acc, t, Lm, rm, Rm, k0, k1, k2);
        relax(acc, t, L0, r0, R0, k3, k4, k5);
        relax(acc, t, Lp, rp, Rp, k6, k7, k8);

        *reinterpret_cast<float4*>(outptr + (size_t)(ROWS_PER_WARP - 1) * Ww) = acc;
    }
}

}  // namespace

extern "C" void kernel_launch(void* const* d_in, const int* in_sizes, int n_in,
                              void* d_out, int out_size) {
    const float* x    = (const float*)d_in[0];
    const float* kern = (const float*)d_in[1];
    const float* gw   = (const float*)d_in[2];
    const float* gb   = (const float*)d_in[3];
    float* out        = (float*)d_out;

    const int planes = in_sizes[0] / (Hh * Ww);  // B * C = 1536
    dynmorph_kernel<<<planes * STRIPS_PER_PLANE, THREADS>>>(x, kern, gw, gb, out);
}

// round 8
// speedup vs baseline: 1.2192x; 1.0344x over previous
#include <cuda_runtime.h>

namespace {

constexpr int Cc = 192;
constexpr int Hh = 128;
constexpr int Ww = 128;
constexpr int ROWS_PER_WARP = 4;
constexpr int WARPS = 4;
constexpr int THREADS = WARPS * 32;
constexpr int ROWS_PER_BLOCK = WARPS * ROWS_PER_WARP;   // 16
constexpr int STRIPS_PER_PLANE = Hh / ROWS_PER_BLOCK;   // 8

__device__ __forceinline__ float tanh_approx(float t) {
    float r; asm("tanh.approx.f32 %0, %1;" : "=f"(r) : "f"(t)); return r;
}
// sigmoid(x*gw+gb) = 0.5*tanh((x*gw+gb)/2) + 0.5, with gw/2, gb/2 prefolded
__device__ __forceinline__ float gate_sig(float v, float a, float b) {
    return fmaf(tanh_approx(fmaf(v, a, b)), 0.5f, 0.5f);
}

// acc = max(acc, patch + t*k) over one input row (halo L/R), one kernel row
__device__ __forceinline__ void relax(float4& acc, const float4& t,
                                      float L, const float4& v, float R,
                                      float kl, float kc, float kr) {
    acc.x = fmaxf(acc.x, fmaf(t.x, kl, L));
    acc.x = fmaxf(acc.x, fmaf(t.x, kc, v.x));
    acc.x = fmaxf(acc.x, fmaf(t.x, kr, v.y));

    acc.y = fmaxf(acc.y, fmaf(t.y, kl, v.x));
    acc.y = fmaxf(acc.y, fmaf(t.y, kc, v.y));
    acc.y = fmaxf(acc.y, fmaf(t.y, kr, v.z));

    acc.z = fmaxf(acc.z, fmaf(t.z, kl, v.y));
    acc.z = fmaxf(acc.z, fmaf(t.z, kc, v.z));
    acc.z = fmaxf(acc.z, fmaf(t.z, kr, v.w));

    acc.w = fmaxf(acc.w, fmaf(t.w, kl, v.z));
    acc.w = fmaxf(acc.w, fmaf(t.w, kc, v.w));
    acc.w = fmaxf(acc.w, fmaf(t.w, kr, R));
}

// same but initializes acc (saves 4 FMNMX)
__device__ __forceinline__ void relax_init(float4& acc, const float4& t,
                                           float L, const float4& v, float R,
                                           float kl, float kc, float kr) {
    acc.x = fmaf(t.x, kc, v.x);
    acc.y = fmaf(t.y, kc, v.y);
    acc.z = fmaf(t.z, kc, v.z);
    acc.w = fmaf(t.w, kc, v.w);

    acc.x = fmaxf(acc.x, fmaf(t.x, kl, L));
    acc.x = fmaxf(acc.x, fmaf(t.x, kr, v.y));

    acc.y = fmaxf(acc.y, fmaf(t.y, kl, v.x));
    acc.y = fmaxf(acc.y, fmaf(t.y, kr, v.z));

    acc.z = fmaxf(acc.z, fmaf(t.z, kl, v.y));
    acc.z = fmaxf(acc.z, fmaf(t.z, kr, v.w));

    acc.w = fmaxf(acc.w, fmaf(t.w, kl, v.z));
    acc.w = fmaxf(acc.w, fmaf(t.w, kr, R));
}

__global__ void __launch_bounds__(THREADS, 12)
dynmorph_kernel(const float* __restrict__ x,
                const float* __restrict__ kern,
                const float* __restrict__ gw,
                const float* __restrict__ gb,
                float* __restrict__ out) {
    const int strip = blockIdx.x;
    const int plane = strip / STRIPS_PER_PLANE;
    const int part  = strip % STRIPS_PER_PLANE;
    const int c     = plane % Cc;
    const int warp  = threadIdx.x >> 5;
    const int lane  = threadIdx.x & 31;

    const float* __restrict__ xp = x   + (size_t)plane * (Hh * Ww);
    float*       __restrict__ op = out + (size_t)plane * (Hh * Ww);

    const float k0 = __ldg(&kern[c * 9 + 0]);
    const float k1 = __ldg(&kern[c * 9 + 1]);
    const float k2 = __ldg(&kern[c * 9 + 2]);
    const float k3 = __ldg(&kern[c * 9 + 3]);
    const float k4 = __ldg(&kern[c * 9 + 4]);
    const float k5 = __ldg(&kern[c * 9 + 5]);
    const float k6 = __ldg(&kern[c * 9 + 6]);
    const float k7 = __ldg(&kern[c * 9 + 7]);
    const float k8 = __ldg(&kern[c * 9 + 8]);
    // fold the /2 of the tanh-sigmoid identity into the gate params
    const float ga  = __ldg(&gw[c]) * 0.5f;
    const float gbp = __ldg(&gb[c]) * 0.5f;

    const int h0  = part * ROWS_PER_BLOCK + warp * ROWS_PER_WARP;
    const int col = lane * 4;

    const float* rowptr = xp + (size_t)h0 * Ww + col;
    float*       outptr = op + (size_t)h0 * Ww + col;

    float4 rm, r0, rp;
    float Lm, Rm, L0, R0, Lp, Rp;

    // row h0-1 (zero pad at top of plane; uniform branch per warp)
    if (h0 == 0) {
        rm = make_float4(0.f, 0.f, 0.f, 0.f);
    } else {
        rm = *reinterpret_cast<const float4*>(rowptr - Ww);
    }
    {
        float l = __shfl_up_sync(0xffffffffu, rm.w, 1);
        float r = __shfl_down_sync(0xffffffffu, rm.x, 1);
        Lm = (lane == 0) ? 0.f : l;
        Rm = (lane == 31) ? 0.f : r;
    }

    // row h0
    r0 = *reinterpret_cast<const float4*>(rowptr);
    {
        float l = __shfl_up_sync(0xffffffffu, r0.w, 1);
        float r = __shfl_down_sync(0xffffffffu, r0.x, 1);
        L0 = (lane == 0) ? 0.f : l;
        R0 = (lane == 31) ? 0.f : r;
    }

    // rr = 0..2: row h+1 = h0+rr+1 <= 127 always in-bounds -> branch-free.
#pragma unroll
    for (int rr = 0; rr < ROWS_PER_WARP - 1; rr++) {
        rp = *reinterpret_cast<const float4*>(rowptr + (size_t)(rr + 1) * Ww);
        {
            float l = __shfl_up_sync(0xffffffffu, rp.w, 1);
            float r = __shfl_down_sync(0xffffffffu, rp.x, 1);
            Lp = (lane == 0) ? 0.f : l;
            Rp = (lane == 31) ? 0.f : r;
        }

        float4 t;
        t.x = gate_sig(r0.x, ga, gbp);
        t.y = gate_sig(r0.y, ga, gbp);
        t.z = gate_sig(r0.z, ga, gbp);
        t.w = gate_sig(r0.w, ga, gbp);

        float4 acc;
        relax_init(acc, t, Lm, rm, Rm, k0, k1, k2);  // row h-1
        relax(acc, t, L0, r0, R0, k3, k4, k5);       // row h
        relax(acc, t, Lp, rp, Rp, k6, k7, k8);       // row h+1

        *reinterpret_cast<float4*>(outptr + (size_t)rr * Ww) = acc;

        rm = r0; Lm = L0; Rm = R0;
        r0 = rp; L0 = Lp; R0 = Rp;
    }

    // epilogue: last row of the strip; row h+1 may be the bottom pad
    {
        const int h = h0 + ROWS_PER_WARP - 1;
        if (h + 1 < Hh) {
            rp = *reinterpret_cast<const float4*>(rowptr + (size_t)ROWS_PER_WARP * Ww);
        } else {
            rp = make_float4(0.f, 0.f, 0.f, 0.f);
        }
        {
            float l = __shfl_up_sync(0xffffffffu, rp.w, 1);
            float r = __shfl_down_sync(0xffffffffu, rp.x, 1);
            Lp = (lane == 0) ? 0.f : l;
            Rp = (lane == 31) ? 0.f : r;
        }

        float4 t;
        t.x = gate_sig(r0.x, ga, gbp);
        t.y = gate_sig(r0.y, ga, gbp);
        t.z = gate_sig(r0.z, ga, gbp);
        t.w = gate_sig(r0.w, ga, gbp);

        float4 acc;
        relax_init(acc, t, Lm, rm, Rm, k0, k1, k2);
        relax(acc, t, L0, r0, R0, k3, k4, k5);
        relax(acc, t, Lp, rp, Rp, k6, k7, k8);

        *reinterpret_cast<float4*>(outptr + (size_t)(ROWS_PER_WARP - 1) * Ww) = acc;
    }
}

}  // namespace

extern "C" void kernel_launch(void* const* d_in, const int* in_sizes, int n_in,
                              void* d_out, int out_size) {
    const float* x    = (const float*)d_in[0];
    const float* kern = (const float*)d_in[1];
    const float* gw   = (const float*)d_in[2];
    const float* gb   = (const float*)d_in[3];
    float* out        = (float*)d_out;

    const int planes = in_sizes[0] / (Hh * Ww);  // B * C = 1536
    dynmorph_kernel<<<planes * STRIPS_PER_PLANE, THREADS>>>(x, kern, gw, gb, out);
}

// round 9
// speedup vs baseline: 1.2203x; 1.0009x over previous
#include <cuda_runtime.h>

namespace {

constexpr int Cc = 192;
constexpr int Hh = 128;
constexpr int Ww = 128;
constexpr int ROWS_PER_WARP = 4;
constexpr int WARPS = 4;
constexpr int THREADS = WARPS * 32;
constexpr int ROWS_PER_BLOCK = WARPS * ROWS_PER_WARP;   // 16
constexpr int STRIPS_PER_PLANE = Hh / ROWS_PER_BLOCK;   // 8
constexpr int NROWS = ROWS_PER_WARP + 2;                // 6 rows live per warp

__device__ __forceinline__ float tanh_approx(float t) {
    float r; asm("tanh.approx.f32 %0, %1;" : "=f"(r) : "f"(t)); return r;
}
// sigmoid(x*gw+gb) = 0.5*tanh((x*gw+gb)/2) + 0.5, with gw/2, gb/2 prefolded
__device__ __forceinline__ float gate_sig(float v, float a, float b) {
    return fmaf(tanh_approx(fmaf(v, a, b)), 0.5f, 0.5f);
}

// acc = max(acc, patch + t*k) over one input row (halo L/R), one kernel row
__device__ __forceinline__ void relax(float4& acc, const float4& t,
                                      float L, const float4& v, float R,
                                      float kl, float kc, float kr) {
    acc.x = fmaxf(acc.x, fmaf(t.x, kl, L));
    acc.x = fmaxf(acc.x, fmaf(t.x, kc, v.x));
    acc.x = fmaxf(acc.x, fmaf(t.x, kr, v.y));

    acc.y = fmaxf(acc.y, fmaf(t.y, kl, v.x));
    acc.y = fmaxf(acc.y, fmaf(t.y, kc, v.y));
    acc.y = fmaxf(acc.y, fmaf(t.y, kr, v.z));

    acc.z = fmaxf(acc.z, fmaf(t.z, kl, v.y));
    acc.z = fmaxf(acc.z, fmaf(t.z, kc, v.z));
    acc.z = fmaxf(acc.z, fmaf(t.z, kr, v.w));

    acc.w = fmaxf(acc.w, fmaf(t.w, kl, v.z));
    acc.w = fmaxf(acc.w, fmaf(t.w, kc, v.w));
    acc.w = fmaxf(acc.w, fmaf(t.w, kr, R));
}

// same but initializes acc (saves 4 FMNMX)
__device__ __forceinline__ void relax_init(float4& acc, const float4& t,
                                           float L, const float4& v, float R,
                                           float kl, float kc, float kr) {
    acc.x = fmaf(t.x, kc, v.x);
    acc.y = fmaf(t.y, kc, v.y);
    acc.z = fmaf(t.z, kc, v.z);
    acc.w = fmaf(t.w, kc, v.w);

    acc.x = fmaxf(acc.x, fmaf(t.x, kl, L));
    acc.x = fmaxf(acc.x, fmaf(t.x, kr, v.y));

    acc.y = fmaxf(acc.y, fmaf(t.y, kl, v.x));
    acc.y = fmaxf(acc.y, fmaf(t.y, kr, v.z));

    acc.z = fmaxf(acc.z, fmaf(t.z, kl, v.y));
    acc.z = fmaxf(acc.z, fmaf(t.z, kr, v.w));

    acc.w = fmaxf(acc.w, fmaf(t.w, kl, v.z));
    acc.w = fmaxf(acc.w, fmaf(t.w, kr, R));
}

__global__ void __launch_bounds__(THREADS, 8)
dynmorph_kernel(const float* __restrict__ x,
                const float* __restrict__ kern,
                const float* __restrict__ gw,
                const float* __restrict__ gb,
                float* __restrict__ out) {
    const int strip = blockIdx.x;
    const int plane = strip / STRIPS_PER_PLANE;
    const int part  = strip % STRIPS_PER_PLANE;
    const int c     = plane % Cc;
    const int warp  = threadIdx.x >> 5;
    const int lane  = threadIdx.x & 31;

    const float* __restrict__ xp = x   + (size_t)plane * (Hh * Ww);
    float*       __restrict__ op = out + (size_t)plane * (Hh * Ww);

    const int h0  = part * ROWS_PER_BLOCK + warp * ROWS_PER_WARP;
    const int col = lane * 4;

    const float* rowptr = xp + (size_t)h0 * Ww + col;
    float*       outptr = op + (size_t)h0 * Ww + col;

    // ---- front-batched loads: all 6 rows in flight at once (MLP=6) ----
    float4 r[NROWS];
    // r[i] holds input row (h0 - 1 + i); boundary rows uniform per warp
    if (h0 == 0) {
        r[0] = make_float4(0.f, 0.f, 0.f, 0.f);
    } else {
        r[0] = *reinterpret_cast<const float4*>(rowptr - Ww);
    }
#pragma unroll
    for (int i = 0; i < ROWS_PER_WARP; i++) {
        // rows h0 .. h0+3: always in-bounds (h0 <= 124)
        r[i + 1] = *reinterpret_cast<const float4*>(rowptr + (size_t)i * Ww);
    }
    if (h0 + ROWS_PER_WARP < Hh) {
        r[NROWS - 1] = *reinterpret_cast<const float4*>(
            rowptr + (size_t)ROWS_PER_WARP * Ww);
    } else {
        r[NROWS - 1] = make_float4(0.f, 0.f, 0.f, 0.f);
    }

    // kernel taps / gate params (L1/L2-hot broadcast loads, overlap the row LDGs)
    const float k0 = __ldg(&kern[c * 9 + 0]);
    const float k1 = __ldg(&kern[c * 9 + 1]);
    const float k2 = __ldg(&kern[c * 9 + 2]);
    const float k3 = __ldg(&kern[c * 9 + 3]);
    const float k4 = __ldg(&kern[c * 9 + 4]);
    const float k5 = __ldg(&kern[c * 9 + 5]);
    const float k6 = __ldg(&kern[c * 9 + 6]);
    const float k7 = __ldg(&kern[c * 9 + 7]);
    const float k8 = __ldg(&kern[c * 9 + 8]);
    const float ga  = __ldg(&gw[c]) * 0.5f;
    const float gbp = __ldg(&gb[c]) * 0.5f;

    // ---- halos via shuffles (after all loads are in flight) ----
    float Lh[NROWS], Rh[NROWS];
#pragma unroll
    for (int i = 0; i < NROWS; i++) {
        float l = __shfl_up_sync(0xffffffffu, r[i].w, 1);
        float rr_ = __shfl_down_sync(0xffffffffu, r[i].x, 1);
        Lh[i] = (lane == 0) ? 0.f : l;
        Rh[i] = (lane == 31) ? 0.f : rr_;
    }

    // ---- compute all 4 output rows from registers, zero memory stalls ----
#pragma unroll
    for (int rr = 0; rr < ROWS_PER_WARP; rr++) {
        const float4& vm = r[rr];
        const float4& v0 = r[rr + 1];
        const float4& vp = r[rr + 2];

        float4 t;
        t.x = gate_sig(v0.x, ga, gbp);
        t.y = gate_sig(v0.y, ga, gbp);
        t.z = gate_sig(v0.z, ga, gbp);
        t.w = gate_sig(v0.w, ga, gbp);

        float4 acc;
        relax_init(acc, t, Lh[rr],     vm, Rh[rr],     k0, k1, k2);
        relax(acc, t, Lh[rr + 1], v0, Rh[rr + 1], k3, k4, k5);
        relax(acc, t, Lh[rr + 2], vp, Rh[rr + 2], k6, k7, k8);

        *reinterpret_cast<float4*>(outptr + (size_t)rr * Ww) = acc;
    }
}

}  // namespace

extern "C" void kernel_launch(void* const* d_in, const int* in_sizes, int n_in,
                              void* d_out, int out_size) {
    const float* x    = (const float*)d_in[0];
    const float* kern = (const float*)d_in[1];
    const float* gw   = (const float*)d_in[2];
    const float* gb   = (const float*)d_in[3];
    float* out        = (float*)d_out;

    const int planes = in_sizes[0] / (Hh * Ww);  // B * C = 1536
    dynmorph_kernel<<<planes * STRIPS_PER_PLANE, THREADS>>>(x, kern, gw, gb, out);
}